// round 1
// baseline (speedup 1.0000x reference)
#include <cuda_runtime.h>
#include <cuda_fp16.h>

// StyleNeuS fused: tri-plane encode + fp16 MLP decode + analytic grad.
// Layout: 8 lanes per point (lane f owns features 4f..4f+3), 4 points per warp.
// Outputs concatenated: sdf[N] | h[N,32] | nablas[N,3] | rgb[N,3]  (fp32)

#define RESV 512

__global__ void __launch_bounds__(256)
styleneus_fused(const float* __restrict__ x,
                const float* __restrict__ planes,
                const float* __restrict__ W1,
                const float* __restrict__ b1,
                const float* __restrict__ W2,
                const float* __restrict__ b2,
                float* __restrict__ out,
                int N)
{
    __shared__ float W1c[1024];  // [i][j] : W1s = float(half(W1)*half(s))
    __shared__ float W1r[1024];  // [j][i] : transposed copy for backward

    const __half sh     = __float2half(0.17677669529663689f);  // np.float16(1/sqrt(32))
    const __half slopeh = __float2half(0.2f);
    const __half zeroh  = __float2half(0.0f);

    const int tid = threadIdx.x;
    for (int idx = tid; idx < 1024; idx += blockDim.x) {
        int i = idx >> 5, j = idx & 31;
        float v = __half2float(__hmul(__float2half(W1[idx]), sh));
        W1c[idx] = v;
        W1r[j * 32 + i] = v;
    }
    __syncthreads();

    const int lane = tid & 31;
    const int f = lane & 7;   // feature-slice index (features 4f..4f+3)
    const int g = lane >> 3;  // point index within warp (0..3)

    // Per-lane constants (fixed j-slice = 4f..4f+3)
    float  w2r[4][4];
    __half w2c0h[4];
    __half b1h[4];
    #pragma unroll
    for (int e = 0; e < 4; e++) {
        int j = 4 * f + e;
        #pragma unroll
        for (int k = 0; k < 4; k++)
            w2r[e][k] = __half2float(__hmul(__float2half(W2[j * 4 + k]), sh));
        w2c0h[e] = __float2half(w2r[e][0]);
        b1h[e]   = __float2half(b1[j]);
    }
    __half b2h[4];
    #pragma unroll
    for (int k = 0; k < 4; k++) b2h[k] = __float2half(b2[k]);

    float* __restrict__ outSdf = out;
    float* __restrict__ outH   = out + (size_t)N;
    float* __restrict__ outNab = out + (size_t)N * 33;
    float* __restrict__ outRgb = out + (size_t)N * 36;

    const int warpsPerCta = blockDim.x >> 5;
    int       warpId      = blockIdx.x * warpsPerCta + (tid >> 5);
    const int warpStride  = gridDim.x * warpsPerCta;

    for (; warpId * 4 < N; warpId += warpStride) {
        int  p     = warpId * 4 + g;
        bool valid = (p < N);
        int  pc    = valid ? p : (N - 1);

        // --- coordinates ---
        float fr[3];
        int   i0[3], i1[3];
        #pragma unroll
        for (int d = 0; d < 3; d++) {
            float xv  = __ldg(&x[pc * 3 + d]);
            float xt  = (xv + 1.0f) * 0.5f;
            float pos = xt * 511.0f;
            float fl  = floorf(pos);
            fr[d] = pos - fl;
            int q = (int)fl;
            q = q < 0 ? 0 : (q > 511 ? 511 : q);
            i0[d] = q;
            i1[d] = (q + 1 > 511) ? 511 : (q + 1);
        }

        // --- encode: h and directional vectors U_d = dh/dx_t[d] (per 4-feat slice) ---
        float hq[4] = {0, 0, 0, 0};
        float U0[4] = {0, 0, 0, 0}, U1[4] = {0, 0, 0, 0}, U2[4] = {0, 0, 0, 0};

        #pragma unroll
        for (int k = 0; k < 3; k++) {
            const int a = (k == 2) ? 1 : 0;
            const int b = (k == 0) ? 1 : 2;
            float fa = fr[a], fb = fr[b];
            const float* pb = planes + (size_t)k * (RESV * RESV * 32);
            int ra0 = i0[a] << 9, ra1 = i1[a] << 9;
            int cb0 = i0[b],      cb1 = i1[b];

            float4 c00 = __ldg(reinterpret_cast<const float4*>(pb + ((size_t)(ra0 + cb0) << 5)) + f);
            float4 c01 = __ldg(reinterpret_cast<const float4*>(pb + ((size_t)(ra0 + cb1) << 5)) + f);
            float4 c10 = __ldg(reinterpret_cast<const float4*>(pb + ((size_t)(ra1 + cb0) << 5)) + f);
            float4 c11 = __ldg(reinterpret_cast<const float4*>(pb + ((size_t)(ra1 + cb1) << 5)) + f);

            float ofa = 1.0f - fa, ofb = 1.0f - fb;
            float w00 = ofa * ofb, w01 = ofa * fb, w10 = fa * ofb, w11 = fa * fb;

            float c0c[4] = {c00.x, c00.y, c00.z, c00.w};
            float c1c[4] = {c01.x, c01.y, c01.z, c01.w};
            float c2c[4] = {c10.x, c10.y, c10.z, c10.w};
            float c3c[4] = {c11.x, c11.y, c11.z, c11.w};

            float dua[4], dub[4];
            #pragma unroll
            for (int c = 0; c < 4; c++) {
                hq[c] = fmaf(w00, c0c[c], hq[c]);
                hq[c] = fmaf(w01, c1c[c], hq[c]);
                hq[c] = fmaf(w10, c2c[c], hq[c]);
                hq[c] = fmaf(w11, c3c[c], hq[c]);
                // d/dfa = (1-fb)(c10-c00) + fb(c11-c01)
                float e1 = c2c[c] - c0c[c];
                float e2 = c3c[c] - c1c[c];
                dua[c] = fmaf(fb, e2 - e1, e1);
                // d/dfb = (1-fa)(c01-c00) + fa(c11-c10)
                float e3 = c1c[c] - c0c[c];
                float e4 = c3c[c] - c2c[c];
                dub[c] = fmaf(fa, e4 - e3, e3);
            }
            #pragma unroll
            for (int c = 0; c < 4; c++) {
                if (k == 0)      { U0[c] += dua[c]; U1[c] += dub[c]; }
                else if (k == 1) { U0[c] += dua[c]; U2[c] += dub[c]; }
                else             { U1[c] += dua[c]; U2[c] += dub[c]; }
            }
        }

        // --- write h (fp32) ---
        if (valid) {
            float4 hv = make_float4(hq[0], hq[1], hq[2], hq[3]);
            *reinterpret_cast<float4*>(outH + (size_t)p * 32 + 4 * f) = hv;
        }

        // --- h -> fp16 rounded values (decoder input) ---
        float hs[4];
        #pragma unroll
        for (int c = 0; c < 4; c++) hs[c] = __half2float(__float2half(hq[c]));

        // --- layer 1: z1_j = sum_i h16_i * W1s[i][j] (fp32 accum) ---
        float acc[4] = {0, 0, 0, 0};
        #pragma unroll
        for (int i = 0; i < 32; i++) {
            float hi = __shfl_sync(0xffffffffu, hs[i & 3], i >> 2, 8);
            float4 wr = *reinterpret_cast<const float4*>(&W1c[i * 32 + 4 * f]);
            acc[0] = fmaf(hi, wr.x, acc[0]);
            acc[1] = fmaf(hi, wr.y, acc[1]);
            acc[2] = fmaf(hi, wr.z, acc[2]);
            acc[3] = fmaf(hi, wr.w, acc[3]);
        }

        // --- activation (fp16 semantics) + layer-2 partials + lrelu cotangent g ---
        float o[4] = {0, 0, 0, 0};
        float gf[4];
        #pragma unroll
        for (int e = 0; e < 4; e++) {
            __half y1h = __hadd(__float2half(acc[e]), b1h[e]);
            bool   neg = __hlt(y1h, zeroh);
            __half ylh = neg ? __hmul(slopeh, y1h) : y1h;
            float  ylf = __half2float(ylh);
            o[0] = fmaf(ylf, w2r[e][0], o[0]);
            o[1] = fmaf(ylf, w2r[e][1], o[1]);
            o[2] = fmaf(ylf, w2r[e][2], o[2]);
            o[3] = fmaf(ylf, w2r[e][3], o[3]);
            __half gh_ = neg ? __hmul(slopeh, w2c0h[e]) : w2c0h[e];
            gf[e] = __half2float(gh_);
        }

        // --- backward: g_h_i = fp16( sum_j W1s[i][j] * g_j ) ---
        float ga[4] = {0, 0, 0, 0};
        #pragma unroll
        for (int j = 0; j < 32; j++) {
            float gj = __shfl_sync(0xffffffffu, gf[j & 3], j >> 2, 8);
            float4 wr = *reinterpret_cast<const float4*>(&W1r[j * 32 + 4 * f]);
            ga[0] = fmaf(gj, wr.x, ga[0]);
            ga[1] = fmaf(gj, wr.y, ga[1]);
            ga[2] = fmaf(gj, wr.z, ga[2]);
            ga[3] = fmaf(gj, wr.w, ga[3]);
        }
        float n0 = 0, n1 = 0, n2 = 0;
        #pragma unroll
        for (int e = 0; e < 4; e++) {
            float gh = __half2float(__float2half(ga[e]));
            n0 = fmaf(gh, U0[e], n0);
            n1 = fmaf(gh, U1[e], n1);
            n2 = fmaf(gh, U2[e], n2);
        }

        // --- 8-lane butterfly reductions (group-local, width 8) ---
        #pragma unroll
        for (int d2 = 1; d2 < 8; d2 <<= 1) {
            o[0] += __shfl_xor_sync(0xffffffffu, o[0], d2, 8);
            o[1] += __shfl_xor_sync(0xffffffffu, o[1], d2, 8);
            o[2] += __shfl_xor_sync(0xffffffffu, o[2], d2, 8);
            o[3] += __shfl_xor_sync(0xffffffffu, o[3], d2, 8);
            n0   += __shfl_xor_sync(0xffffffffu, n0,   d2, 8);
            n1   += __shfl_xor_sync(0xffffffffu, n1,   d2, 8);
            n2   += __shfl_xor_sync(0xffffffffu, n2,   d2, 8);
        }

        // --- finalize + writes ---
        if (valid) {
            if (f == 0) {
                __half s0 = __hadd(__float2half(o[0]), b2h[0]);
                outSdf[p] = __half2float(s0);
            }
            if (f >= 1 && f <= 3) {
                float z = (f == 1) ? o[1] : ((f == 2) ? o[2] : o[3]);
                __half ok = __hadd(__float2half(z), b2h[f]);
                float ofv = __half2float(ok);
                outRgb[(size_t)p * 3 + (f - 1)] = (tanhf(ofv) + 1.0f) * 0.5f;
            }
            if (f <= 2) {
                float nv = (f == 0) ? n0 : ((f == 1) ? n1 : n2);
                outNab[(size_t)p * 3 + f] = nv * 511.0f;
            }
        }
    }
}

extern "C" void kernel_launch(void* const* d_in, const int* in_sizes, int n_in,
                              void* d_out, int out_size)
{
    const float* x      = (const float*)d_in[0];
    const float* planes = (const float*)d_in[1];
    const float* W1     = (const float*)d_in[2];
    const float* b1     = (const float*)d_in[3];
    const float* W2     = (const float*)d_in[4];
    const float* b2     = (const float*)d_in[5];
    float* out = (float*)d_out;

    int N = in_sizes[0] / 3;

    const int threads = 256;
    const int ptsPerCta = (threads / 32) * 4;  // 32 points per CTA iteration
    int blocksFull = (N + ptsPerCta - 1) / ptsPerCta;
    int blocks = blocksFull < 4736 ? blocksFull : 4736;

    styleneus_fused<<<blocks, threads>>>(x, planes, W1, b1, W2, b2, out, N);
}

// round 2
// speedup vs baseline: 1.3608x; 1.3608x over previous
#include <cuda_runtime.h>
#include <cuda_fp16.h>

// StyleNeuS fused: tri-plane encode + fp16 MLP decode + analytic grad.
// Layout: 8 lanes per point (lane f owns features 4f..4f+3), 4 points per warp.
// MLP weights in smem as fp16, consumed via mixed-precision fma.rn.f32.f16.
// Outputs concatenated: sdf[N] | h[N,32] | nablas[N,3] | rgb[N,3]  (fp32)

#define RESV 512

__device__ __forceinline__ float ffma16(float acc, unsigned short a, unsigned short b) {
    asm("fma.rn.f32.f16 %0, %1, %2, %0;" : "+f"(acc) : "h"(a), "h"(b));
    return acc;
}
__device__ __forceinline__ void unpack2(unsigned v, unsigned short& lo, unsigned short& hi) {
    asm("mov.b32 {%0, %1}, %2;" : "=h"(lo), "=h"(hi) : "r"(v));
}

__global__ void __launch_bounds__(256)
styleneus_fused(const float* __restrict__ x,
                const float* __restrict__ planes,
                const float* __restrict__ W1,
                const float* __restrict__ b1,
                const float* __restrict__ W2,
                const float* __restrict__ b2,
                float* __restrict__ out,
                int N)
{
    __shared__ __half W1h[1024];   // [i][j] fp16 value of float16(W1)*float16(s)
    __shared__ __half W1rh[1024];  // [j][i] transposed copy for backward

    const __half sh     = __float2half(0.17677669529663689f);  // np.float16(1/sqrt(32))
    const __half slopeh = __float2half(0.2f);
    const __half zeroh  = __float2half(0.0f);

    const int tid = threadIdx.x;
    for (int idx = tid; idx < 1024; idx += blockDim.x) {
        int i = idx >> 5, j = idx & 31;
        __half wv = __hmul(__float2half(W1[idx]), sh);
        W1h[idx] = wv;
        W1rh[j * 32 + i] = wv;
    }
    __syncthreads();

    const int lane = tid & 31;
    const int f = lane & 7;   // feature-slice index (features 4f..4f+3)
    const int g = lane >> 3;  // point index within warp (0..3)

    // Per-lane constants (fixed j-slice = 4f..4f+3)
    unsigned short w2h[4][4];   // fp16 bits of float16(W2[j][k])*s
    unsigned short w2c0[4];     // column 0 (sdf cotangent seed)
    __half b1h[4];
    #pragma unroll
    for (int e = 0; e < 4; e++) {
        int j = 4 * f + e;
        #pragma unroll
        for (int k = 0; k < 4; k++) {
            __half wv = __hmul(__float2half(W2[j * 4 + k]), sh);
            w2h[e][k] = __half_as_ushort(wv);
        }
        w2c0[e] = w2h[e][0];
        b1h[e]  = __float2half(b1[j]);
    }
    __half b2h[4];
    #pragma unroll
    for (int k = 0; k < 4; k++) b2h[k] = __float2half(b2[k]);

    float* __restrict__ outSdf = out;
    float* __restrict__ outH   = out + (size_t)N;
    float* __restrict__ outNab = out + (size_t)N * 33;
    float* __restrict__ outRgb = out + (size_t)N * 36;

    const int warpsPerCta = blockDim.x >> 5;
    int       warpId      = blockIdx.x * warpsPerCta + (tid >> 5);
    const int warpStride  = gridDim.x * warpsPerCta;

    for (; warpId * 4 < N; warpId += warpStride) {
        int  p     = warpId * 4 + g;
        bool valid = (p < N);
        int  pc    = valid ? p : (N - 1);

        // --- coordinates ---
        float fr[3];
        int   i0[3], i1[3];
        #pragma unroll
        for (int d = 0; d < 3; d++) {
            float xv  = __ldg(&x[pc * 3 + d]);
            float xt  = (xv + 1.0f) * 0.5f;
            float pos = xt * 511.0f;
            float fl  = floorf(pos);
            fr[d] = pos - fl;
            int q = (int)fl;
            q = q < 0 ? 0 : (q > 511 ? 511 : q);
            i0[d] = q;
            i1[d] = (q + 1 > 511) ? 511 : (q + 1);
        }

        // --- encode: h and directional vectors U_d = dh/dx_t[d] (per 4-feat slice) ---
        float hq[4] = {0, 0, 0, 0};
        float U0[4] = {0, 0, 0, 0}, U1[4] = {0, 0, 0, 0}, U2[4] = {0, 0, 0, 0};

        #pragma unroll
        for (int k = 0; k < 3; k++) {
            const int a = (k == 2) ? 1 : 0;
            const int b = (k == 0) ? 1 : 2;
            float fa = fr[a], fb = fr[b];
            const float* pb = planes + (size_t)k * (RESV * RESV * 32);
            int ra0 = i0[a] << 9, ra1 = i1[a] << 9;
            int cb0 = i0[b],      cb1 = i1[b];

            float4 c00 = __ldg(reinterpret_cast<const float4*>(pb + ((size_t)(ra0 + cb0) << 5)) + f);
            float4 c01 = __ldg(reinterpret_cast<const float4*>(pb + ((size_t)(ra0 + cb1) << 5)) + f);
            float4 c10 = __ldg(reinterpret_cast<const float4*>(pb + ((size_t)(ra1 + cb0) << 5)) + f);
            float4 c11 = __ldg(reinterpret_cast<const float4*>(pb + ((size_t)(ra1 + cb1) << 5)) + f);

            float ofa = 1.0f - fa, ofb = 1.0f - fb;
            float w00 = ofa * ofb, w01 = ofa * fb, w10 = fa * ofb, w11 = fa * fb;

            float c0c[4] = {c00.x, c00.y, c00.z, c00.w};
            float c1c[4] = {c01.x, c01.y, c01.z, c01.w};
            float c2c[4] = {c10.x, c10.y, c10.z, c10.w};
            float c3c[4] = {c11.x, c11.y, c11.z, c11.w};

            float dua[4], dub[4];
            #pragma unroll
            for (int c = 0; c < 4; c++) {
                hq[c] = fmaf(w00, c0c[c], hq[c]);
                hq[c] = fmaf(w01, c1c[c], hq[c]);
                hq[c] = fmaf(w10, c2c[c], hq[c]);
                hq[c] = fmaf(w11, c3c[c], hq[c]);
                float e1 = c2c[c] - c0c[c];
                float e2 = c3c[c] - c1c[c];
                dua[c] = fmaf(fb, e2 - e1, e1);
                float e3 = c1c[c] - c0c[c];
                float e4 = c3c[c] - c2c[c];
                dub[c] = fmaf(fa, e4 - e3, e3);
            }
            #pragma unroll
            for (int c = 0; c < 4; c++) {
                if (k == 0)      { U0[c] += dua[c]; U1[c] += dub[c]; }
                else if (k == 1) { U0[c] += dua[c]; U2[c] += dub[c]; }
                else             { U1[c] += dua[c]; U2[c] += dub[c]; }
            }
        }

        // --- write h (fp32) ---
        if (valid) {
            float4 hv = make_float4(hq[0], hq[1], hq[2], hq[3]);
            *reinterpret_cast<float4*>(outH + (size_t)p * 32 + 4 * f) = hv;
        }

        // --- h -> fp16, packed as two half2 ---
        unsigned hpk[2];
        {
            __half2 a = __halves2half2(__float2half(hq[0]), __float2half(hq[1]));
            __half2 b = __halves2half2(__float2half(hq[2]), __float2half(hq[3]));
            hpk[0] = *reinterpret_cast<unsigned*>(&a);
            hpk[1] = *reinterpret_cast<unsigned*>(&b);
        }

        // --- layer 1: z1_j = sum_i h16_i * W1s[i][j] (fp32 accum, fp16 operands) ---
        float acc[4] = {0, 0, 0, 0};
        #pragma unroll
        for (int i2 = 0; i2 < 16; i2++) {
            unsigned hv = __shfl_sync(0xffffffffu, hpk[i2 & 1], i2 >> 1, 8);
            unsigned short hlo, hhi; unpack2(hv, hlo, hhi);
            int i = 2 * i2;
            uint2 wa = *reinterpret_cast<const uint2*>(&W1h[i * 32 + 4 * f]);
            uint2 wb = *reinterpret_cast<const uint2*>(&W1h[(i + 1) * 32 + 4 * f]);
            unsigned short a0, a1, a2, a3, b0, b1_, b2_, b3;
            unpack2(wa.x, a0, a1); unpack2(wa.y, a2, a3);
            unpack2(wb.x, b0, b1_); unpack2(wb.y, b2_, b3);
            acc[0] = ffma16(acc[0], hlo, a0);  acc[0] = ffma16(acc[0], hhi, b0);
            acc[1] = ffma16(acc[1], hlo, a1);  acc[1] = ffma16(acc[1], hhi, b1_);
            acc[2] = ffma16(acc[2], hlo, a2);  acc[2] = ffma16(acc[2], hhi, b2_);
            acc[3] = ffma16(acc[3], hlo, a3);  acc[3] = ffma16(acc[3], hhi, b3);
        }

        // --- activation (fp16) + layer-2 partials + lrelu cotangent g (fp16) ---
        float o[4] = {0, 0, 0, 0};
        __half gh4[4];
        #pragma unroll
        for (int e = 0; e < 4; e++) {
            __half y1h = __hadd(__float2half(acc[e]), b1h[e]);
            bool   neg = __hlt(y1h, zeroh);
            __half ylh = neg ? __hmul(slopeh, y1h) : y1h;
            unsigned short ylb = __half_as_ushort(ylh);
            o[0] = ffma16(o[0], ylb, w2h[e][0]);
            o[1] = ffma16(o[1], ylb, w2h[e][1]);
            o[2] = ffma16(o[2], ylb, w2h[e][2]);
            o[3] = ffma16(o[3], ylb, w2h[e][3]);
            __half gw = __ushort_as_half(w2c0[e]);
            gh4[e] = neg ? __hmul(slopeh, gw) : gw;
        }
        unsigned gpk[2];
        {
            __half2 a = __halves2half2(gh4[0], gh4[1]);
            __half2 b = __halves2half2(gh4[2], gh4[3]);
            gpk[0] = *reinterpret_cast<unsigned*>(&a);
            gpk[1] = *reinterpret_cast<unsigned*>(&b);
        }

        // --- backward: g_h_i = fp16( sum_j W1s[i][j] * g_j ) ---
        float ga[4] = {0, 0, 0, 0};
        #pragma unroll
        for (int j2 = 0; j2 < 16; j2++) {
            unsigned gv = __shfl_sync(0xffffffffu, gpk[j2 & 1], j2 >> 1, 8);
            unsigned short glo, ghi; unpack2(gv, glo, ghi);
            int j = 2 * j2;
            uint2 wa = *reinterpret_cast<const uint2*>(&W1rh[j * 32 + 4 * f]);
            uint2 wb = *reinterpret_cast<const uint2*>(&W1rh[(j + 1) * 32 + 4 * f]);
            unsigned short a0, a1, a2, a3, b0, b1_, b2_, b3;
            unpack2(wa.x, a0, a1); unpack2(wa.y, a2, a3);
            unpack2(wb.x, b0, b1_); unpack2(wb.y, b2_, b3);
            ga[0] = ffma16(ga[0], glo, a0);  ga[0] = ffma16(ga[0], ghi, b0);
            ga[1] = ffma16(ga[1], glo, a1);  ga[1] = ffma16(ga[1], ghi, b1_);
            ga[2] = ffma16(ga[2], glo, a2);  ga[2] = ffma16(ga[2], ghi, b2_);
            ga[3] = ffma16(ga[3], glo, a3);  ga[3] = ffma16(ga[3], ghi, b3);
        }
        float n0 = 0, n1 = 0, n2 = 0;
        #pragma unroll
        for (int e = 0; e < 4; e++) {
            float gh = __half2float(__float2half(ga[e]));
            n0 = fmaf(gh, U0[e], n0);
            n1 = fmaf(gh, U1[e], n1);
            n2 = fmaf(gh, U2[e], n2);
        }

        // --- 8-lane butterfly reductions (group-local, width 8) ---
        #pragma unroll
        for (int d2 = 1; d2 < 8; d2 <<= 1) {
            o[0] += __shfl_xor_sync(0xffffffffu, o[0], d2, 8);
            o[1] += __shfl_xor_sync(0xffffffffu, o[1], d2, 8);
            o[2] += __shfl_xor_sync(0xffffffffu, o[2], d2, 8);
            o[3] += __shfl_xor_sync(0xffffffffu, o[3], d2, 8);
            n0   += __shfl_xor_sync(0xffffffffu, n0,   d2, 8);
            n1   += __shfl_xor_sync(0xffffffffu, n1,   d2, 8);
            n2   += __shfl_xor_sync(0xffffffffu, n2,   d2, 8);
        }

        // --- finalize + writes ---
        if (valid) {
            if (f == 0) {
                __half s0 = __hadd(__float2half(o[0]), b2h[0]);
                outSdf[p] = __half2float(s0);
            }
            if (f >= 1 && f <= 3) {
                float z = (f == 1) ? o[1] : ((f == 2) ? o[2] : o[3]);
                __half ok = __hadd(__float2half(z), b2h[f]);
                float ofv = __half2float(ok);
                outRgb[(size_t)p * 3 + (f - 1)] = (tanhf(ofv) + 1.0f) * 0.5f;
            }
            if (f <= 2) {
                float nv = (f == 0) ? n0 : ((f == 1) ? n1 : n2);
                outNab[(size_t)p * 3 + f] = nv * 511.0f;
            }
        }
    }
}

extern "C" void kernel_launch(void* const* d_in, const int* in_sizes, int n_in,
                              void* d_out, int out_size)
{
    const float* x      = (const float*)d_in[0];
    const float* planes = (const float*)d_in[1];
    const float* W1     = (const float*)d_in[2];
    const float* b1     = (const float*)d_in[3];
    const float* W2     = (const float*)d_in[4];
    const float* b2     = (const float*)d_in[5];
    float* out = (float*)d_out;

    int N = in_sizes[0] / 3;

    const int threads = 256;
    const int ptsPerCta = (threads / 32) * 4;  // 32 points per CTA iteration
    int blocksFull = (N + ptsPerCta - 1) / ptsPerCta;
    int blocks = blocksFull < 4736 ? blocksFull : 4736;

    styleneus_fused<<<blocks, threads>>>(x, planes, W1, b1, W2, b2, out, N);
}

// round 3
// speedup vs baseline: 1.6398x; 1.2050x over previous
#include <cuda_runtime.h>
#include <cuda_fp16.h>

#define RESV 512
#define FULLM 0xffffffffu

__device__ __forceinline__ void mma16816(float& d0, float& d1, float& d2, float& d3,
                                         unsigned a0, unsigned a1, unsigned a2, unsigned a3,
                                         unsigned b0, unsigned b1) {
    asm volatile("mma.sync.aligned.m16n8k16.row.col.f32.f16.f16.f32 "
                 "{%0,%1,%2,%3},{%4,%5,%6,%7},{%8,%9},{%0,%1,%2,%3};"
                 : "+f"(d0), "+f"(d1), "+f"(d2), "+f"(d3)
                 : "r"(a0), "r"(a1), "r"(a2), "r"(a3), "r"(b0), "r"(b1));
}

__device__ __forceinline__ unsigned packh2(__half lo, __half hi) {
    __half2 h = __halves2half2(lo, hi);
    return *reinterpret_cast<unsigned*>(&h);
}

__global__ void __launch_bounds__(256, 2)
styleneus_fused(const float* __restrict__ x,
                const float* __restrict__ planes,
                const float* __restrict__ W1,
                const float* __restrict__ b1,
                const float* __restrict__ W2,
                const float* __restrict__ b2,
                float* __restrict__ out,
                int N)
{
    // per-warp h/gh staging: 8 rows x 40 halves (pad for banks)
    __shared__ __half stage[8 * 320];

    const __half  sh     = __float2half(0.17677669529663689f);  // fp16(1/sqrt(32))
    const __half  hzero  = __float2half(0.0f);
    const __half2 zero2  = __float2half2_rn(0.0f);
    const __half2 slope2 = __float2half2_rn(0.2f);
    const __half  slopeh = __float2half(0.2f);

    const int tid  = threadIdx.x;
    const int lane = tid & 31;
    const int f    = lane & 7;   // feature-slice (gather layout)
    const int g    = lane >> 3;  // point-in-pass (gather layout)
    const int tig  = lane & 3;   // mma thread-in-group
    const int gid  = lane >> 2;  // mma group id (row for A/C, col for B)

    __half* st = stage + (tid >> 5) * 320;

    // ---- weight fragments (once per warp) ----
    // w1s(i,j) = fp16(fp16(W1[i][j]) * s)
    #define W1S(i, j) __hmul(__float2half(__ldg(&W1[(i) * 32 + (j)])), sh)
    #define W2S(i, j) __hmul(__float2half(__ldg(&W2[(i) * 4 + (j)])), sh)

    unsigned w1b[2][4][2];   // forward  B frags: B[k][n] = W1s[k][n]
    unsigned w1tb[2][4][2];  // backward B frags: B[k][n] = W1s[n][k]
    #pragma unroll
    for (int kt = 0; kt < 2; kt++)
        #pragma unroll
        for (int nt = 0; nt < 4; nt++) {
            int k0 = 16 * kt + 2 * tig;
            int jc = 8 * nt + gid;
            w1b[kt][nt][0] = packh2(W1S(k0,     jc), W1S(k0 + 1, jc));
            w1b[kt][nt][1] = packh2(W1S(k0 + 8, jc), W1S(k0 + 9, jc));
            w1tb[kt][nt][0] = packh2(W1S(jc, k0),     W1S(jc, k0 + 1));
            w1tb[kt][nt][1] = packh2(W1S(jc, k0 + 8), W1S(jc, k0 + 9));
        }
    unsigned w2b[2][2];      // layer-2 B frags (N padded 4->8)
    #pragma unroll
    for (int kt = 0; kt < 2; kt++) {
        int k0 = 16 * kt + 2 * tig;
        if (gid < 4) {
            w2b[kt][0] = packh2(W2S(k0,     gid), W2S(k0 + 1, gid));
            w2b[kt][1] = packh2(W2S(k0 + 8, gid), W2S(k0 + 9, gid));
        } else {
            w2b[kt][0] = 0; w2b[kt][1] = 0;
        }
    }
    // activation constants in C layout (cols 8*nt + 2*tig, +1)
    __half2 b1h2[4], wpos[4], wneg[4];
    #pragma unroll
    for (int nt = 0; nt < 4; nt++) {
        int c0 = 8 * nt + 2 * tig;
        b1h2[nt] = __halves2half2(__float2half(__ldg(&b1[c0])), __float2half(__ldg(&b1[c0 + 1])));
        __half2 w0 = __halves2half2(W2S(c0, 0), W2S(c0 + 1, 0));
        wpos[nt] = w0;
        wneg[nt] = __hmul2(__halves2half2(slopeh, slopeh), w0);
    }
    __half b2lo = hzero, b2hi = hzero;
    if (tig < 2) {
        b2lo = __float2half(__ldg(&b2[2 * tig]));
        b2hi = __float2half(__ldg(&b2[2 * tig + 1]));
    }

    float* __restrict__ outSdf = out;
    float* __restrict__ outH   = out + (size_t)N;
    float* __restrict__ outNab = out + (size_t)N * 33;
    float* __restrict__ outRgb = out + (size_t)N * 36;

    const int warpsPerCta = blockDim.x >> 5;
    int       warpId      = blockIdx.x * warpsPerCta + (tid >> 5);
    const int warpStride  = gridDim.x * warpsPerCta;

    for (; warpId * 8 < N; warpId += warpStride) {
        const int base = warpId * 8;

        // ---------- encode: 2 passes of 4 points, gather layout ----------
        float U[2][3][4];
        #pragma unroll
        for (int r = 0; r < 2; r++) {
            int  p     = base + 4 * r + g;
            bool valid = (p < N);
            int  pc    = valid ? p : (N - 1);

            float fr[3];
            int   i0[3], i1[3];
            #pragma unroll
            for (int d = 0; d < 3; d++) {
                float xv  = __ldg(&x[pc * 3 + d]);
                float pos = (xv + 1.0f) * 0.5f * 511.0f;
                float fl  = floorf(pos);
                fr[d] = pos - fl;
                int q = (int)fl;
                q = q < 0 ? 0 : (q > 511 ? 511 : q);
                i0[d] = q;
                i1[d] = (q + 1 > 511) ? 511 : (q + 1);
            }

            float hq[4] = {0, 0, 0, 0};
            #pragma unroll
            for (int d = 0; d < 3; d++)
                #pragma unroll
                for (int c = 0; c < 4; c++) U[r][d][c] = 0.0f;

            #pragma unroll
            for (int k = 0; k < 3; k++) {
                const int a = (k == 2) ? 1 : 0;
                const int b = (k == 0) ? 1 : 2;
                float fa = fr[a], fb = fr[b];
                const float* pb = planes + (size_t)k * (RESV * RESV * 32);
                int ra0 = i0[a] << 9, ra1 = i1[a] << 9;
                int cb0 = i0[b],      cb1 = i1[b];

                float4 c00 = __ldg(reinterpret_cast<const float4*>(pb + ((size_t)(ra0 + cb0) << 5)) + f);
                float4 c01 = __ldg(reinterpret_cast<const float4*>(pb + ((size_t)(ra0 + cb1) << 5)) + f);
                float4 c10 = __ldg(reinterpret_cast<const float4*>(pb + ((size_t)(ra1 + cb0) << 5)) + f);
                float4 c11 = __ldg(reinterpret_cast<const float4*>(pb + ((size_t)(ra1 + cb1) << 5)) + f);

                float ofa = 1.0f - fa, ofb = 1.0f - fb;
                float w00 = ofa * ofb, w01 = ofa * fb, w10 = fa * ofb, w11 = fa * fb;

                float c0c[4] = {c00.x, c00.y, c00.z, c00.w};
                float c1c[4] = {c01.x, c01.y, c01.z, c01.w};
                float c2c[4] = {c10.x, c10.y, c10.z, c10.w};
                float c3c[4] = {c11.x, c11.y, c11.z, c11.w};

                const int da = (k == 0) ? 0 : ((k == 1) ? 0 : 1);  // dim of fa
                const int db = (k == 0) ? 1 : 2;                   // dim of fb
                #pragma unroll
                for (int c = 0; c < 4; c++) {
                    hq[c] = fmaf(w00, c0c[c], hq[c]);
                    hq[c] = fmaf(w01, c1c[c], hq[c]);
                    hq[c] = fmaf(w10, c2c[c], hq[c]);
                    hq[c] = fmaf(w11, c3c[c], hq[c]);
                    float e1 = c2c[c] - c0c[c];
                    float e2 = c3c[c] - c1c[c];
                    U[r][da][c] += fmaf(fb, e2 - e1, e1);
                    float e3 = c1c[c] - c0c[c];
                    float e4 = c3c[c] - c2c[c];
                    U[r][db][c] += fmaf(fa, e4 - e3, e3);
                }
            }

            if (valid) {
                float4 hv = make_float4(hq[0], hq[1], hq[2], hq[3]);
                *reinterpret_cast<float4*>(outH + (size_t)p * 32 + 4 * f) = hv;
            }

            // stage h16 row (4r+g), halves 4f..4f+3
            unsigned h0 = packh2(__float2half(hq[0]), __float2half(hq[1]));
            unsigned h1 = packh2(__float2half(hq[2]), __float2half(hq[3]));
            *reinterpret_cast<uint2*>(st + (4 * r + g) * 40 + 4 * f) = make_uint2(h0, h1);
        }
        __syncwarp();

        // ---------- forward mma: Z[8,32] = H * W1s ----------
        unsigned aF[2][2];
        #pragma unroll
        for (int kt = 0; kt < 2; kt++) {
            aF[kt][0] = *reinterpret_cast<const unsigned*>(st + gid * 40 + 2 * tig + 16 * kt);
            aF[kt][1] = *reinterpret_cast<const unsigned*>(st + gid * 40 + 2 * tig + 16 * kt + 8);
        }
        float dF[4][4];
        #pragma unroll
        for (int nt = 0; nt < 4; nt++) {
            dF[nt][0] = dF[nt][1] = dF[nt][2] = dF[nt][3] = 0.0f;
            #pragma unroll
            for (int kt = 0; kt < 2; kt++)
                mma16816(dF[nt][0], dF[nt][1], dF[nt][2], dF[nt][3],
                         aF[kt][0], 0u, aF[kt][1], 0u,
                         w1b[kt][nt][0], w1b[kt][nt][1]);
        }

        // ---------- activation + cotangent (C layout) ----------
        unsigned y2[4], g2[4];
        #pragma unroll
        for (int nt = 0; nt < 4; nt++) {
            __half2 z2 = __floats2half2_rn(dF[nt][0], dF[nt][1]);
            __half2 yb = __hadd2(z2, b1h2[nt]);
            __half2 yl = __hfma2(__hmin2(yb, zero2), slope2, __hmax2(yb, zero2));
            y2[nt] = *reinterpret_cast<unsigned*>(&yl);
            __half glo = __hlt(__low2half(yb),  hzero) ? __low2half(wneg[nt])  : __low2half(wpos[nt]);
            __half ghi = __hlt(__high2half(yb), hzero) ? __high2half(wneg[nt]) : __high2half(wpos[nt]);
            g2[nt] = packh2(glo, ghi);
        }

        // ---------- layer 2: O[8,4] = Y * W2s ----------
        float o0 = 0, o1 = 0, o2d = 0, o3d = 0;
        #pragma unroll
        for (int kt = 0; kt < 2; kt++)
            mma16816(o0, o1, o2d, o3d, y2[2 * kt], 0u, y2[2 * kt + 1], 0u,
                     w2b[kt][0], w2b[kt][1]);

        // ---------- backward: GH[8,32] = G * W1s^T ----------
        float dB[4][4];
        #pragma unroll
        for (int nt = 0; nt < 4; nt++) {
            dB[nt][0] = dB[nt][1] = dB[nt][2] = dB[nt][3] = 0.0f;
            #pragma unroll
            for (int kt = 0; kt < 2; kt++)
                mma16816(dB[nt][0], dB[nt][1], dB[nt][2], dB[nt][3],
                         g2[2 * kt], 0u, g2[2 * kt + 1], 0u,
                         w1tb[kt][nt][0], w1tb[kt][nt][1]);
        }
        __syncwarp();

        // stage gh16 (C layout -> rows)
        #pragma unroll
        for (int nt = 0; nt < 4; nt++) {
            unsigned pk = packh2(__float2half(dB[nt][0]), __float2half(dB[nt][1]));
            *reinterpret_cast<unsigned*>(st + gid * 40 + 8 * nt + 2 * tig) = pk;
        }
        __syncwarp();

        // ---------- nablas: gh . U per pass, reduce over 8 lanes ----------
        float nb[2][3];
        #pragma unroll
        for (int r = 0; r < 2; r++) {
            uint2 gw = *reinterpret_cast<const uint2*>(st + (4 * r + g) * 40 + 4 * f);
            __half2 glo2 = *reinterpret_cast<__half2*>(&gw.x);
            __half2 ghi2 = *reinterpret_cast<__half2*>(&gw.y);
            float gv[4];
            gv[0] = __half2float(__low2half(glo2));
            gv[1] = __half2float(__high2half(glo2));
            gv[2] = __half2float(__low2half(ghi2));
            gv[3] = __half2float(__high2half(ghi2));
            #pragma unroll
            for (int d = 0; d < 3; d++) {
                float s = 0;
                #pragma unroll
                for (int e = 0; e < 4; e++) s = fmaf(gv[e], U[r][d][e], s);
                nb[r][d] = s;
            }
        }
        __syncwarp();

        // reduce-scatter over 8 lanes: v[f] = {n00,n01,n02,0, n10,n11,n12,0}[f] summed
        {
            float v0 = nb[0][0], v1 = nb[0][1], v2 = nb[0][2], v3 = 0.0f;
            float v4 = nb[1][0], v5 = nb[1][1], v6 = nb[1][2], v7 = 0.0f;
            bool hi4 = (f & 4) != 0;
            float t;
            t = __shfl_xor_sync(FULLM, hi4 ? v0 : v4, 4, 8); if (hi4) v4 += t; else v0 += t;
            t = __shfl_xor_sync(FULLM, hi4 ? v1 : v5, 4, 8); if (hi4) v5 += t; else v1 += t;
            t = __shfl_xor_sync(FULLM, hi4 ? v2 : v6, 4, 8); if (hi4) v6 += t; else v2 += t;
            float w0 = hi4 ? v4 : v0, w1 = hi4 ? v5 : v1, w2 = hi4 ? v6 : v2, w3 = hi4 ? v7 : v3;
            bool hi2 = (f & 2) != 0;
            t = __shfl_xor_sync(FULLM, hi2 ? w0 : w2, 2, 8); if (hi2) w2 += t; else w0 += t;
            t = __shfl_xor_sync(FULLM, hi2 ? w1 : w3, 2, 8); if (hi2) w3 += t; else w1 += t;
            float u0 = hi2 ? w2 : w0, u1 = hi2 ? w3 : w1;
            bool hi1 = (f & 1) != 0;
            t = __shfl_xor_sync(FULLM, hi1 ? u0 : u1, 1, 8); if (hi1) u1 += t; else u0 += t;
            float res = hi1 ? u1 : u0;

            int fm = f & 3;
            if (fm < 3) {
                int pp = base + ((f >> 2) << 2) + g;
                if (pp < N) outNab[(size_t)pp * 3 + fm] = res * 511.0f;
            }
        }

        // ---------- sdf / rgb ----------
        if (tig < 2) {
            int pp = base + gid;
            if (pp < N) {
                __half a0 = __hadd(__float2half(o0), b2lo);
                __half a1 = __hadd(__float2half(o1), b2hi);
                if (tig == 0) {
                    outSdf[pp] = __half2float(a0);
                    outRgb[(size_t)pp * 3 + 0] = (tanhf(__half2float(a1)) + 1.0f) * 0.5f;
                } else {
                    outRgb[(size_t)pp * 3 + 1] = (tanhf(__half2float(a0)) + 1.0f) * 0.5f;
                    outRgb[(size_t)pp * 3 + 2] = (tanhf(__half2float(a1)) + 1.0f) * 0.5f;
                }
            }
        }
    }
    #undef W1S
    #undef W2S
}

extern "C" void kernel_launch(void* const* d_in, const int* in_sizes, int n_in,
                              void* d_out, int out_size)
{
    const float* x      = (const float*)d_in[0];
    const float* planes = (const float*)d_in[1];
    const float* W1     = (const float*)d_in[2];
    const float* b1     = (const float*)d_in[3];
    const float* W2     = (const float*)d_in[4];
    const float* b2     = (const float*)d_in[5];
    float* out = (float*)d_out;

    int N = in_sizes[0] / 3;

    const int threads = 256;
    const int ptsPerCta = (threads / 32) * 8;  // 64 points per CTA iteration
    int blocksFull = (N + ptsPerCta - 1) / ptsPerCta;
    int blocks = blocksFull < 4736 ? blocksFull : 4736;

    styleneus_fused<<<blocks, threads>>>(x, planes, W1, b1, W2, b2, out, N);
}

// round 4
// speedup vs baseline: 1.8903x; 1.1528x over previous
#include <cuda_runtime.h>
#include <cuda_fp16.h>

#define RESV 512
#define FULLM 0xffffffffu

__device__ __forceinline__ void mma16816(float& d0, float& d1, float& d2, float& d3,
                                         unsigned a0, unsigned a1, unsigned a2, unsigned a3,
                                         unsigned b0, unsigned b1) {
    asm volatile("mma.sync.aligned.m16n8k16.row.col.f32.f16.f16.f32 "
                 "{%0,%1,%2,%3},{%4,%5,%6,%7},{%8,%9},{%0,%1,%2,%3};"
                 : "+f"(d0), "+f"(d1), "+f"(d2), "+f"(d3)
                 : "r"(a0), "r"(a1), "r"(a2), "r"(a3), "r"(b0), "r"(b1));
}

__device__ __forceinline__ unsigned packh2(__half lo, __half hi) {
    __half2 h = __halves2half2(lo, hi);
    return *reinterpret_cast<unsigned*>(&h);
}

__global__ void __launch_bounds__(256, 3)
styleneus_fused(const float* __restrict__ x,
                const float* __restrict__ planes,
                const float* __restrict__ W1,
                const float* __restrict__ b1,
                const float* __restrict__ W2,
                const float* __restrict__ b2,
                float* __restrict__ out,
                int N)
{
    // lane-indexed weight fragments: per lane 36 words
    //  [0..15]  w1b[kt][nt][h]  (forward B frags)
    //  [16..31] w1tb[kt][nt][h] (backward B frags)
    //  [32..35] w2b[kt][h]      (layer-2 B frags)
    __shared__ unsigned wfrag[32 * 36];
    // per-warp h/gh staging: 8 rows x 40 halves
    __shared__ __half stage[8 * 320];
    // per-thread pass-0 U backup (12 floats)
    __shared__ float uback[256 * 12];

    const __half  sh     = __float2half(0.17677669529663689f);  // fp16(1/sqrt(32))
    const __half  hzero  = __float2half(0.0f);
    const __half2 zero2  = __float2half2_rn(0.0f);
    const __half2 slope2 = __float2half2_rn(0.2f);
    const __half  slopeh = __float2half(0.2f);

    const int tid  = threadIdx.x;
    const int lane = tid & 31;
    const int f    = lane & 7;   // feature-slice (gather layout)
    const int g    = lane >> 3;  // point-in-pass (gather layout)
    const int tig  = lane & 3;   // mma thread-in-group
    const int gid  = lane >> 2;  // mma group id

    #define W1S(i, j) __hmul(__float2half(__ldg(&W1[(i) * 32 + (j)])), sh)
    #define W2S(i, j) __hmul(__float2half(__ldg(&W2[(i) * 4 + (j)])), sh)

    // ---- build weight fragments once per CTA (warp 0) ----
    if (tid < 32) {
        unsigned* wl = wfrag + lane * 36;
        #pragma unroll
        for (int kt = 0; kt < 2; kt++)
            #pragma unroll
            for (int nt = 0; nt < 4; nt++) {
                int k0 = 16 * kt + 2 * tig;
                int jc = 8 * nt + gid;
                wl[kt * 8 + nt * 2 + 0] = packh2(W1S(k0,     jc), W1S(k0 + 1, jc));
                wl[kt * 8 + nt * 2 + 1] = packh2(W1S(k0 + 8, jc), W1S(k0 + 9, jc));
                wl[16 + kt * 8 + nt * 2 + 0] = packh2(W1S(jc, k0),     W1S(jc, k0 + 1));
                wl[16 + kt * 8 + nt * 2 + 1] = packh2(W1S(jc, k0 + 8), W1S(jc, k0 + 9));
            }
        #pragma unroll
        for (int kt = 0; kt < 2; kt++) {
            int k0 = 16 * kt + 2 * tig;
            if (gid < 4) {
                wl[32 + kt * 2 + 0] = packh2(W2S(k0,     gid), W2S(k0 + 1, gid));
                wl[32 + kt * 2 + 1] = packh2(W2S(k0 + 8, gid), W2S(k0 + 9, gid));
            } else {
                wl[32 + kt * 2 + 0] = 0;
                wl[32 + kt * 2 + 1] = 0;
            }
        }
    }
    __syncthreads();

    // per-lane activation constants (C layout: cols 8*nt + 2*tig, +1)
    __half2 b1h2[4], wpos[4];
    #pragma unroll
    for (int nt = 0; nt < 4; nt++) {
        int c0 = 8 * nt + 2 * tig;
        b1h2[nt] = __halves2half2(__float2half(__ldg(&b1[c0])), __float2half(__ldg(&b1[c0 + 1])));
        wpos[nt] = __halves2half2(W2S(c0, 0), W2S(c0 + 1, 0));
    }
    __half2 b2p = zero2;
    if (tig < 2)
        b2p = __halves2half2(__float2half(__ldg(&b2[2 * tig])), __float2half(__ldg(&b2[2 * tig + 1])));

    float* __restrict__ outSdf = out;
    float* __restrict__ outH   = out + (size_t)N;
    float* __restrict__ outNab = out + (size_t)N * 33;
    float* __restrict__ outRgb = out + (size_t)N * 36;

    __half* st = stage + (tid >> 5) * 320;
    const uint4*  wl4 = reinterpret_cast<const uint4*>(wfrag + lane * 36);
    float4*       ub4 = reinterpret_cast<float4*>(uback + tid * 12);

    const int warpsPerCta = blockDim.x >> 5;
    int       warpId      = blockIdx.x * warpsPerCta + (tid >> 5);
    const int warpStride  = gridDim.x * warpsPerCta;

    for (; warpId * 8 < N; warpId += warpStride) {
        const int base = warpId * 8;

        // ---------- encode: 2 passes of 4 points, gather layout ----------
        float U[3][4];  // current pass's directional vectors
        #pragma unroll
        for (int r = 0; r < 2; r++) {
            int  p     = base + 4 * r + g;
            bool valid = (p < N);
            int  pc    = valid ? p : (N - 1);

            float fr[3];
            int   i0[3], i1[3];
            #pragma unroll
            for (int d = 0; d < 3; d++) {
                float xv  = __ldg(&x[pc * 3 + d]);
                float pos = (xv + 1.0f) * 0.5f * 511.0f;
                float fl  = floorf(pos);
                fr[d] = pos - fl;
                int q = (int)fl;
                q = q < 0 ? 0 : (q > 511 ? 511 : q);
                i0[d] = q;
                i1[d] = (q + 1 > 511) ? 511 : (q + 1);
            }

            float hq[4] = {0, 0, 0, 0};
            #pragma unroll
            for (int d = 0; d < 3; d++)
                #pragma unroll
                for (int c = 0; c < 4; c++) U[d][c] = 0.0f;

            #pragma unroll
            for (int k = 0; k < 3; k++) {
                const int a = (k == 2) ? 1 : 0;
                const int b = (k == 0) ? 1 : 2;
                float fa = fr[a], fb = fr[b];
                const float* pb = planes + (size_t)k * (RESV * RESV * 32);
                int ra0 = i0[a] << 9, ra1 = i1[a] << 9;
                int cb0 = i0[b],      cb1 = i1[b];

                float4 c00 = __ldg(reinterpret_cast<const float4*>(pb + ((size_t)(ra0 + cb0) << 5)) + f);
                float4 c01 = __ldg(reinterpret_cast<const float4*>(pb + ((size_t)(ra0 + cb1) << 5)) + f);
                float4 c10 = __ldg(reinterpret_cast<const float4*>(pb + ((size_t)(ra1 + cb0) << 5)) + f);
                float4 c11 = __ldg(reinterpret_cast<const float4*>(pb + ((size_t)(ra1 + cb1) << 5)) + f);

                float ofa = 1.0f - fa, ofb = 1.0f - fb;
                float w00 = ofa * ofb, w01 = ofa * fb, w10 = fa * ofb, w11 = fa * fb;

                float c0c[4] = {c00.x, c00.y, c00.z, c00.w};
                float c1c[4] = {c01.x, c01.y, c01.z, c01.w};
                float c2c[4] = {c10.x, c10.y, c10.z, c10.w};
                float c3c[4] = {c11.x, c11.y, c11.z, c11.w};

                const int da = (k == 2) ? 1 : 0;  // dim index of fa
                const int db = (k == 0) ? 1 : 2;  // dim index of fb
                #pragma unroll
                for (int c = 0; c < 4; c++) {
                    hq[c] = fmaf(w00, c0c[c], hq[c]);
                    hq[c] = fmaf(w01, c1c[c], hq[c]);
                    hq[c] = fmaf(w10, c2c[c], hq[c]);
                    hq[c] = fmaf(w11, c3c[c], hq[c]);
                    float e1 = c2c[c] - c0c[c];
                    float e2 = c3c[c] - c1c[c];
                    U[da][c] += fmaf(fb, e2 - e1, e1);
                    float e3 = c1c[c] - c0c[c];
                    float e4 = c3c[c] - c2c[c];
                    U[db][c] += fmaf(fa, e4 - e3, e3);
                }
            }

            if (valid) {
                float4 hv = make_float4(hq[0], hq[1], hq[2], hq[3]);
                *reinterpret_cast<float4*>(outH + (size_t)p * 32 + 4 * f) = hv;
            }

            // stage h16 row (4r+g)
            unsigned h0 = packh2(__float2half(hq[0]), __float2half(hq[1]));
            unsigned h1 = packh2(__float2half(hq[2]), __float2half(hq[3]));
            *reinterpret_cast<uint2*>(st + (4 * r + g) * 40 + 4 * f) = make_uint2(h0, h1);

            if (r == 0) {
                // park pass-0 U in smem, free the registers for pass 1
                ub4[0] = make_float4(U[0][0], U[0][1], U[0][2], U[0][3]);
                ub4[1] = make_float4(U[1][0], U[1][1], U[1][2], U[1][3]);
                ub4[2] = make_float4(U[2][0], U[2][1], U[2][2], U[2][3]);
            }
        }
        __syncwarp();

        // ---------- forward mma: Z[8,32] = H * W1s ----------
        unsigned aF[2][2];
        #pragma unroll
        for (int kt = 0; kt < 2; kt++) {
            aF[kt][0] = *reinterpret_cast<const unsigned*>(st + gid * 40 + 2 * tig + 16 * kt);
            aF[kt][1] = *reinterpret_cast<const unsigned*>(st + gid * 40 + 2 * tig + 16 * kt + 8);
        }
        unsigned wfb[16];
        *reinterpret_cast<uint4*>(wfb +  0) = wl4[0];
        *reinterpret_cast<uint4*>(wfb +  4) = wl4[1];
        *reinterpret_cast<uint4*>(wfb +  8) = wl4[2];
        *reinterpret_cast<uint4*>(wfb + 12) = wl4[3];
        float dF[4][4];
        #pragma unroll
        for (int nt = 0; nt < 4; nt++) {
            dF[nt][0] = dF[nt][1] = dF[nt][2] = dF[nt][3] = 0.0f;
            #pragma unroll
            for (int kt = 0; kt < 2; kt++)
                mma16816(dF[nt][0], dF[nt][1], dF[nt][2], dF[nt][3],
                         aF[kt][0], 0u, aF[kt][1], 0u,
                         wfb[kt * 8 + nt * 2], wfb[kt * 8 + nt * 2 + 1]);
        }

        // ---------- activation + cotangent (C layout) ----------
        unsigned y2[4], g2[4];
        #pragma unroll
        for (int nt = 0; nt < 4; nt++) {
            __half2 z2 = __floats2half2_rn(dF[nt][0], dF[nt][1]);
            __half2 yb = __hadd2(z2, b1h2[nt]);
            __half2 yl = __hfma2(__hmin2(yb, zero2), slope2, __hmax2(yb, zero2));
            y2[nt] = *reinterpret_cast<unsigned*>(&yl);
            __half2 wneg = __hmul2(slope2, wpos[nt]);
            __half glo = __hlt(__low2half(yb),  hzero) ? __low2half(wneg)  : __low2half(wpos[nt]);
            __half ghi = __hlt(__high2half(yb), hzero) ? __high2half(wneg) : __high2half(wpos[nt]);
            g2[nt] = packh2(glo, ghi);
        }

        // ---------- layer 2: O[8,4] = Y * W2s ----------
        float o0 = 0, o1 = 0, o2d = 0, o3d = 0;
        {
            uint4 w2f = wl4[8];  // words 32..35
            mma16816(o0, o1, o2d, o3d, y2[0], 0u, y2[1], 0u, w2f.x, w2f.y);
            mma16816(o0, o1, o2d, o3d, y2[2], 0u, y2[3], 0u, w2f.z, w2f.w);
        }

        // ---------- backward: GH[8,32] = G * W1s^T ----------
        unsigned wbb[16];
        *reinterpret_cast<uint4*>(wbb +  0) = wl4[4];
        *reinterpret_cast<uint4*>(wbb +  4) = wl4[5];
        *reinterpret_cast<uint4*>(wbb +  8) = wl4[6];
        *reinterpret_cast<uint4*>(wbb + 12) = wl4[7];
        float dB[4][4];
        #pragma unroll
        for (int nt = 0; nt < 4; nt++) {
            dB[nt][0] = dB[nt][1] = dB[nt][2] = dB[nt][3] = 0.0f;
            #pragma unroll
            for (int kt = 0; kt < 2; kt++)
                mma16816(dB[nt][0], dB[nt][1], dB[nt][2], dB[nt][3],
                         g2[2 * kt], 0u, g2[2 * kt + 1], 0u,
                         wbb[kt * 8 + nt * 2], wbb[kt * 8 + nt * 2 + 1]);
        }
        __syncwarp();

        // stage gh16 (C layout -> rows)
        #pragma unroll
        for (int nt = 0; nt < 4; nt++) {
            unsigned pk = packh2(__float2half(dB[nt][0]), __float2half(dB[nt][1]));
            *reinterpret_cast<unsigned*>(st + gid * 40 + 8 * nt + 2 * tig) = pk;
        }
        __syncwarp();

        // ---------- nablas: gh . U per pass, reduce over 8 lanes ----------
        float nb[2][3];
        #pragma unroll
        for (int r = 0; r < 2; r++) {
            uint2 gw = *reinterpret_cast<const uint2*>(st + (4 * r + g) * 40 + 4 * f);
            __half2 glo2 = *reinterpret_cast<__half2*>(&gw.x);
            __half2 ghi2 = *reinterpret_cast<__half2*>(&gw.y);
            float gv[4];
            gv[0] = __half2float(__low2half(glo2));
            gv[1] = __half2float(__high2half(glo2));
            gv[2] = __half2float(__low2half(ghi2));
            gv[3] = __half2float(__high2half(ghi2));
            if (r == 0) {
                float4 u0 = ub4[0], u1 = ub4[1], u2 = ub4[2];
                nb[0][0] = fmaf(gv[3], u0.w, fmaf(gv[2], u0.z, fmaf(gv[1], u0.y, gv[0] * u0.x)));
                nb[0][1] = fmaf(gv[3], u1.w, fmaf(gv[2], u1.z, fmaf(gv[1], u1.y, gv[0] * u1.x)));
                nb[0][2] = fmaf(gv[3], u2.w, fmaf(gv[2], u2.z, fmaf(gv[1], u2.y, gv[0] * u2.x)));
            } else {
                #pragma unroll
                for (int d = 0; d < 3; d++) {
                    float s = 0;
                    #pragma unroll
                    for (int e = 0; e < 4; e++) s = fmaf(gv[e], U[d][e], s);
                    nb[1][d] = s;
                }
            }
        }
        __syncwarp();

        // reduce-scatter over 8 lanes
        {
            float v0 = nb[0][0], v1 = nb[0][1], v2 = nb[0][2], v3 = 0.0f;
            float v4 = nb[1][0], v5 = nb[1][1], v6 = nb[1][2], v7 = 0.0f;
            bool hi4 = (f & 4) != 0;
            float t;
            t = __shfl_xor_sync(FULLM, hi4 ? v0 : v4, 4, 8); if (hi4) v4 += t; else v0 += t;
            t = __shfl_xor_sync(FULLM, hi4 ? v1 : v5, 4, 8); if (hi4) v5 += t; else v1 += t;
            t = __shfl_xor_sync(FULLM, hi4 ? v2 : v6, 4, 8); if (hi4) v6 += t; else v2 += t;
            float w0 = hi4 ? v4 : v0, w1 = hi4 ? v5 : v1, w2 = hi4 ? v6 : v2, w3 = hi4 ? v7 : v3;
            bool hi2 = (f & 2) != 0;
            t = __shfl_xor_sync(FULLM, hi2 ? w0 : w2, 2, 8); if (hi2) w2 += t; else w0 += t;
            t = __shfl_xor_sync(FULLM, hi2 ? w1 : w3, 2, 8); if (hi2) w3 += t; else w1 += t;
            float u0 = hi2 ? w2 : w0, u1 = hi2 ? w3 : w1;
            bool hi1 = (f & 1) != 0;
            t = __shfl_xor_sync(FULLM, hi1 ? u0 : u1, 1, 8); if (hi1) u1 += t; else u0 += t;
            float res = hi1 ? u1 : u0;

            int fm = f & 3;
            if (fm < 3) {
                int pp = base + ((f >> 2) << 2) + g;
                if (pp < N) outNab[(size_t)pp * 3 + fm] = res * 511.0f;
            }
        }

        // ---------- sdf / rgb ----------
        if (tig < 2) {
            int pp = base + gid;
            if (pp < N) {
                __half2 oa = __hadd2(__floats2half2_rn(o0, o1), b2p);
                float a0 = __half2float(__low2half(oa));
                float a1 = __half2float(__high2half(oa));
                if (tig == 0) {
                    outSdf[pp] = a0;
                    outRgb[(size_t)pp * 3 + 0] = (tanhf(a1) + 1.0f) * 0.5f;
                } else {
                    outRgb[(size_t)pp * 3 + 1] = (tanhf(a0) + 1.0f) * 0.5f;
                    outRgb[(size_t)pp * 3 + 2] = (tanhf(a1) + 1.0f) * 0.5f;
                }
            }
        }
    }
    #undef W1S
    #undef W2S
}

extern "C" void kernel_launch(void* const* d_in, const int* in_sizes, int n_in,
                              void* d_out, int out_size)
{
    const float* x      = (const float*)d_in[0];
    const float* planes = (const float*)d_in[1];
    const float* W1     = (const float*)d_in[2];
    const float* b1     = (const float*)d_in[3];
    const float* W2     = (const float*)d_in[4];
    const float* b2     = (const float*)d_in[5];
    float* out = (float*)d_out;

    int N = in_sizes[0] / 3;

    const int threads = 256;
    const int ptsPerCta = (threads / 32) * 8;  // 64 points per CTA iteration
    int blocksFull = (N + ptsPerCta - 1) / ptsPerCta;
    int blocks = blocksFull < 4736 ? blocksFull : 4736;

    styleneus_fused<<<blocks, threads>>>(x, planes, W1, b1, W2, b2, out, N);
}

// round 6
// speedup vs baseline: 1.8985x; 1.0043x over previous
#include <cuda_runtime.h>
#include <cuda_fp16.h>

#define RESV 512
#define FULLM 0xffffffffu

__device__ __forceinline__ void mma16816(float& d0, float& d1, float& d2, float& d3,
                                         unsigned a0, unsigned a1, unsigned a2, unsigned a3,
                                         unsigned b0, unsigned b1) {
    asm volatile("mma.sync.aligned.m16n8k16.row.col.f32.f16.f16.f32 "
                 "{%0,%1,%2,%3},{%4,%5,%6,%7},{%8,%9},{%0,%1,%2,%3};"
                 : "+f"(d0), "+f"(d1), "+f"(d2), "+f"(d3)
                 : "r"(a0), "r"(a1), "r"(a2), "r"(a3), "r"(b0), "r"(b1));
}

__device__ __forceinline__ unsigned packh2(__half lo, __half hi) {
    __half2 h = __halves2half2(lo, hi);
    return *reinterpret_cast<unsigned*>(&h);
}

// L2 evict-last policy descriptor (built once per thread)
__device__ __forceinline__ unsigned long long mk_evict_last_policy() {
    unsigned long long pol;
    asm("createpolicy.fractional.L2::evict_last.b64 %0, 1.0;" : "=l"(pol));
    return pol;
}

// plane gather: non-coherent load with evict-last L2 cache hint
__device__ __forceinline__ float4 ldg_plane(const float4* p, unsigned long long pol) {
    float4 v;
    asm volatile("ld.global.nc.L2::cache_hint.v4.f32 {%0,%1,%2,%3}, [%4], %5;"
                 : "=f"(v.x), "=f"(v.y), "=f"(v.z), "=f"(v.w) : "l"(p), "l"(pol));
    return v;
}

__global__ void __launch_bounds__(256, 3)
styleneus_fused(const float* __restrict__ x,
                const float* __restrict__ planes,
                const float* __restrict__ W1,
                const float* __restrict__ b1,
                const float* __restrict__ W2,
                const float* __restrict__ b2,
                float* __restrict__ out,
                int N)
{
    // lane-indexed weight fragments: per lane 36 words
    __shared__ unsigned wfrag[32 * 36];
    // per-warp h/gh staging: 8 rows x 40 halves
    __shared__ __half stage[8 * 320];
    // per-thread pass-0 U backup (12 floats)
    __shared__ float uback[256 * 12];

    const __half  sh     = __float2half(0.17677669529663689f);  // fp16(1/sqrt(32))
    const __half  hzero  = __float2half(0.0f);
    const __half2 zero2  = __float2half2_rn(0.0f);
    const __half2 slope2 = __float2half2_rn(0.2f);

    const unsigned long long evlast = mk_evict_last_policy();

    const int tid  = threadIdx.x;
    const int lane = tid & 31;
    const int f    = lane & 7;   // feature-slice (gather layout)
    const int g    = lane >> 3;  // point-in-pass (gather layout)
    const int tig  = lane & 3;   // mma thread-in-group
    const int gid  = lane >> 2;  // mma group id

    #define W1S(i, j) __hmul(__float2half(__ldg(&W1[(i) * 32 + (j)])), sh)
    #define W2S(i, j) __hmul(__float2half(__ldg(&W2[(i) * 4 + (j)])), sh)

    // ---- build weight fragments once per CTA (warp 0) ----
    if (tid < 32) {
        unsigned* wl = wfrag + lane * 36;
        #pragma unroll
        for (int kt = 0; kt < 2; kt++)
            #pragma unroll
            for (int nt = 0; nt < 4; nt++) {
                int k0 = 16 * kt + 2 * tig;
                int jc = 8 * nt + gid;
                wl[kt * 8 + nt * 2 + 0] = packh2(W1S(k0,     jc), W1S(k0 + 1, jc));
                wl[kt * 8 + nt * 2 + 1] = packh2(W1S(k0 + 8, jc), W1S(k0 + 9, jc));
                wl[16 + kt * 8 + nt * 2 + 0] = packh2(W1S(jc, k0),     W1S(jc, k0 + 1));
                wl[16 + kt * 8 + nt * 2 + 1] = packh2(W1S(jc, k0 + 8), W1S(jc, k0 + 9));
            }
        #pragma unroll
        for (int kt = 0; kt < 2; kt++) {
            int k0 = 16 * kt + 2 * tig;
            if (gid < 4) {
                wl[32 + kt * 2 + 0] = packh2(W2S(k0,     gid), W2S(k0 + 1, gid));
                wl[32 + kt * 2 + 1] = packh2(W2S(k0 + 8, gid), W2S(k0 + 9, gid));
            } else {
                wl[32 + kt * 2 + 0] = 0;
                wl[32 + kt * 2 + 1] = 0;
            }
        }
    }
    __syncthreads();

    // per-lane activation constants (C layout: cols 8*nt + 2*tig, +1)
    __half2 b1h2[4], wpos[4];
    #pragma unroll
    for (int nt = 0; nt < 4; nt++) {
        int c0 = 8 * nt + 2 * tig;
        b1h2[nt] = __halves2half2(__float2half(__ldg(&b1[c0])), __float2half(__ldg(&b1[c0 + 1])));
        wpos[nt] = __halves2half2(W2S(c0, 0), W2S(c0 + 1, 0));
    }
    __half2 b2p = zero2;
    if (tig < 2)
        b2p = __halves2half2(__float2half(__ldg(&b2[2 * tig])), __float2half(__ldg(&b2[2 * tig + 1])));

    float* __restrict__ outSdf = out;
    float* __restrict__ outH   = out + (size_t)N;
    float* __restrict__ outNab = out + (size_t)N * 33;
    float* __restrict__ outRgb = out + (size_t)N * 36;

    __half* st = stage + (tid >> 5) * 320;
    const uint4*  wl4 = reinterpret_cast<const uint4*>(wfrag + lane * 36);
    float4*       ub4 = reinterpret_cast<float4*>(uback + tid * 12);

    const int warpsPerCta = blockDim.x >> 5;
    int       warpId      = blockIdx.x * warpsPerCta + (tid >> 5);
    const int warpStride  = gridDim.x * warpsPerCta;

    for (; warpId * 8 < N; warpId += warpStride) {
        const int base = warpId * 8;

        // ---------- encode: 2 passes of 4 points, gather layout ----------
        float U[3][4];
        #pragma unroll
        for (int r = 0; r < 2; r++) {
            int  p     = base + 4 * r + g;
            bool valid = (p < N);
            int  pc    = valid ? p : (N - 1);

            float fr[3];
            int   i0[3], i1[3];
            #pragma unroll
            for (int d = 0; d < 3; d++) {
                float xv  = __ldcs(&x[pc * 3 + d]);
                float pos = (xv + 1.0f) * 0.5f * 511.0f;
                float fl  = floorf(pos);
                fr[d] = pos - fl;
                int q = (int)fl;
                q = q < 0 ? 0 : (q > 511 ? 511 : q);
                i0[d] = q;
                i1[d] = (q + 1 > 511) ? 511 : (q + 1);
            }

            float hq[4] = {0, 0, 0, 0};
            #pragma unroll
            for (int d = 0; d < 3; d++)
                #pragma unroll
                for (int c = 0; c < 4; c++) U[d][c] = 0.0f;

            #pragma unroll
            for (int k = 0; k < 3; k++) {
                const int a = (k == 2) ? 1 : 0;
                const int b = (k == 0) ? 1 : 2;
                float fa = fr[a], fb = fr[b];
                const float* pb = planes + (size_t)k * (RESV * RESV * 32);
                int ra0 = i0[a] << 9, ra1 = i1[a] << 9;
                int cb0 = i0[b],      cb1 = i1[b];

                float4 c00 = ldg_plane(reinterpret_cast<const float4*>(pb + ((size_t)(ra0 + cb0) << 5)) + f, evlast);
                float4 c01 = ldg_plane(reinterpret_cast<const float4*>(pb + ((size_t)(ra0 + cb1) << 5)) + f, evlast);
                float4 c10 = ldg_plane(reinterpret_cast<const float4*>(pb + ((size_t)(ra1 + cb0) << 5)) + f, evlast);
                float4 c11 = ldg_plane(reinterpret_cast<const float4*>(pb + ((size_t)(ra1 + cb1) << 5)) + f, evlast);

                float ofa = 1.0f - fa, ofb = 1.0f - fb;
                float w00 = ofa * ofb, w01 = ofa * fb, w10 = fa * ofb, w11 = fa * fb;

                float c0c[4] = {c00.x, c00.y, c00.z, c00.w};
                float c1c[4] = {c01.x, c01.y, c01.z, c01.w};
                float c2c[4] = {c10.x, c10.y, c10.z, c10.w};
                float c3c[4] = {c11.x, c11.y, c11.z, c11.w};

                const int da = (k == 2) ? 1 : 0;  // dim index of fa
                const int db = (k == 0) ? 1 : 2;  // dim index of fb
                #pragma unroll
                for (int c = 0; c < 4; c++) {
                    hq[c] = fmaf(w00, c0c[c], hq[c]);
                    hq[c] = fmaf(w01, c1c[c], hq[c]);
                    hq[c] = fmaf(w10, c2c[c], hq[c]);
                    hq[c] = fmaf(w11, c3c[c], hq[c]);
                    float e1 = c2c[c] - c0c[c];
                    float e2 = c3c[c] - c1c[c];
                    U[da][c] += fmaf(fb, e2 - e1, e1);
                    float e3 = c1c[c] - c0c[c];
                    float e4 = c3c[c] - c2c[c];
                    U[db][c] += fmaf(fa, e4 - e3, e3);
                }
            }

            if (valid) {
                float4 hv = make_float4(hq[0], hq[1], hq[2], hq[3]);
                __stcs(reinterpret_cast<float4*>(outH + (size_t)p * 32 + 4 * f), hv);
            }

            // stage h16 row (4r+g)
            unsigned h0 = packh2(__float2half(hq[0]), __float2half(hq[1]));
            unsigned h1 = packh2(__float2half(hq[2]), __float2half(hq[3]));
            *reinterpret_cast<uint2*>(st + (4 * r + g) * 40 + 4 * f) = make_uint2(h0, h1);

            if (r == 0) {
                ub4[0] = make_float4(U[0][0], U[0][1], U[0][2], U[0][3]);
                ub4[1] = make_float4(U[1][0], U[1][1], U[1][2], U[1][3]);
                ub4[2] = make_float4(U[2][0], U[2][1], U[2][2], U[2][3]);
            }
        }
        __syncwarp();

        // ---------- forward mma: Z[8,32] = H * W1s ----------
        unsigned aF[2][2];
        #pragma unroll
        for (int kt = 0; kt < 2; kt++) {
            aF[kt][0] = *reinterpret_cast<const unsigned*>(st + gid * 40 + 2 * tig + 16 * kt);
            aF[kt][1] = *reinterpret_cast<const unsigned*>(st + gid * 40 + 2 * tig + 16 * kt + 8);
        }
        unsigned wfb[16];
        *reinterpret_cast<uint4*>(wfb +  0) = wl4[0];
        *reinterpret_cast<uint4*>(wfb +  4) = wl4[1];
        *reinterpret_cast<uint4*>(wfb +  8) = wl4[2];
        *reinterpret_cast<uint4*>(wfb + 12) = wl4[3];
        float dF[4][4];
        #pragma unroll
        for (int nt = 0; nt < 4; nt++) {
            dF[nt][0] = dF[nt][1] = dF[nt][2] = dF[nt][3] = 0.0f;
            #pragma unroll
            for (int kt = 0; kt < 2; kt++)
                mma16816(dF[nt][0], dF[nt][1], dF[nt][2], dF[nt][3],
                         aF[kt][0], 0u, aF[kt][1], 0u,
                         wfb[kt * 8 + nt * 2], wfb[kt * 8 + nt * 2 + 1]);
        }

        // ---------- activation + cotangent (C layout) ----------
        unsigned y2[4], g2[4];
        #pragma unroll
        for (int nt = 0; nt < 4; nt++) {
            __half2 z2 = __floats2half2_rn(dF[nt][0], dF[nt][1]);
            __half2 yb = __hadd2(z2, b1h2[nt]);
            __half2 yl = __hfma2(__hmin2(yb, zero2), slope2, __hmax2(yb, zero2));
            y2[nt] = *reinterpret_cast<unsigned*>(&yl);
            __half2 wneg = __hmul2(slope2, wpos[nt]);
            __half glo = __hlt(__low2half(yb),  hzero) ? __low2half(wneg)  : __low2half(wpos[nt]);
            __half ghi = __hlt(__high2half(yb), hzero) ? __high2half(wneg) : __high2half(wpos[nt]);
            g2[nt] = packh2(glo, ghi);
        }

        // ---------- layer 2: O[8,4] = Y * W2s ----------
        float o0 = 0, o1 = 0, o2d = 0, o3d = 0;
        {
            uint4 w2f = wl4[8];
            mma16816(o0, o1, o2d, o3d, y2[0], 0u, y2[1], 0u, w2f.x, w2f.y);
            mma16816(o0, o1, o2d, o3d, y2[2], 0u, y2[3], 0u, w2f.z, w2f.w);
        }

        // ---------- backward: GH[8,32] = G * W1s^T ----------
        unsigned wbb[16];
        *reinterpret_cast<uint4*>(wbb +  0) = wl4[4];
        *reinterpret_cast<uint4*>(wbb +  4) = wl4[5];
        *reinterpret_cast<uint4*>(wbb +  8) = wl4[6];
        *reinterpret_cast<uint4*>(wbb + 12) = wl4[7];
        float dB[4][4];
        #pragma unroll
        for (int nt = 0; nt < 4; nt++) {
            dB[nt][0] = dB[nt][1] = dB[nt][2] = dB[nt][3] = 0.0f;
            #pragma unroll
            for (int kt = 0; kt < 2; kt++)
                mma16816(dB[nt][0], dB[nt][1], dB[nt][2], dB[nt][3],
                         g2[2 * kt], 0u, g2[2 * kt + 1], 0u,
                         wbb[kt * 8 + nt * 2], wbb[kt * 8 + nt * 2 + 1]);
        }
        __syncwarp();

        // stage gh16 (C layout -> rows)
        #pragma unroll
        for (int nt = 0; nt < 4; nt++) {
            unsigned pk = packh2(__float2half(dB[nt][0]), __float2half(dB[nt][1]));
            *reinterpret_cast<unsigned*>(st + gid * 40 + 8 * nt + 2 * tig) = pk;
        }
        __syncwarp();

        // ---------- nablas: gh . U per pass, reduce over 8 lanes ----------
        float nb[2][3];
        #pragma unroll
        for (int r = 0; r < 2; r++) {
            uint2 gw = *reinterpret_cast<const uint2*>(st + (4 * r + g) * 40 + 4 * f);
            __half2 glo2 = *reinterpret_cast<__half2*>(&gw.x);
            __half2 ghi2 = *reinterpret_cast<__half2*>(&gw.y);
            float gv[4];
            gv[0] = __half2float(__low2half(glo2));
            gv[1] = __half2float(__high2half(glo2));
            gv[2] = __half2float(__low2half(ghi2));
            gv[3] = __half2float(__high2half(ghi2));
            if (r == 0) {
                float4 u0 = ub4[0], u1 = ub4[1], u2 = ub4[2];
                nb[0][0] = fmaf(gv[3], u0.w, fmaf(gv[2], u0.z, fmaf(gv[1], u0.y, gv[0] * u0.x)));
                nb[0][1] = fmaf(gv[3], u1.w, fmaf(gv[2], u1.z, fmaf(gv[1], u1.y, gv[0] * u1.x)));
                nb[0][2] = fmaf(gv[3], u2.w, fmaf(gv[2], u2.z, fmaf(gv[1], u2.y, gv[0] * u2.x)));
            } else {
                #pragma unroll
                for (int d = 0; d < 3; d++) {
                    float s = 0;
                    #pragma unroll
                    for (int e = 0; e < 4; e++) s = fmaf(gv[e], U[d][e], s);
                    nb[1][d] = s;
                }
            }
        }
        __syncwarp();

        // reduce-scatter over 8 lanes
        {
            float v0 = nb[0][0], v1 = nb[0][1], v2 = nb[0][2], v3 = 0.0f;
            float v4 = nb[1][0], v5 = nb[1][1], v6 = nb[1][2], v7 = 0.0f;
            bool hi4 = (f & 4) != 0;
            float t;
            t = __shfl_xor_sync(FULLM, hi4 ? v0 : v4, 4, 8); if (hi4) v4 += t; else v0 += t;
            t = __shfl_xor_sync(FULLM, hi4 ? v1 : v5, 4, 8); if (hi4) v5 += t; else v1 += t;
            t = __shfl_xor_sync(FULLM, hi4 ? v2 : v6, 4, 8); if (hi4) v6 += t; else v2 += t;
            float w0 = hi4 ? v4 : v0, w1 = hi4 ? v5 : v1, w2 = hi4 ? v6 : v2, w3 = hi4 ? v7 : v3;
            bool hi2 = (f & 2) != 0;
            t = __shfl_xor_sync(FULLM, hi2 ? w0 : w2, 2, 8); if (hi2) w2 += t; else w0 += t;
            t = __shfl_xor_sync(FULLM, hi2 ? w1 : w3, 2, 8); if (hi2) w3 += t; else w1 += t;
            float u0 = hi2 ? w2 : w0, u1 = hi2 ? w3 : w1;
            bool hi1 = (f & 1) != 0;
            t = __shfl_xor_sync(FULLM, hi1 ? u0 : u1, 1, 8); if (hi1) u1 += t; else u0 += t;
            float res = hi1 ? u1 : u0;

            int fm = f & 3;
            if (fm < 3) {
                int pp = base + ((f >> 2) << 2) + g;
                if (pp < N) __stcs(&outNab[(size_t)pp * 3 + fm], res * 511.0f);
            }
        }

        // ---------- sdf / rgb ----------
        if (tig < 2) {
            int pp = base + gid;
            if (pp < N) {
                __half2 oa = __hadd2(__floats2half2_rn(o0, o1), b2p);
                float a0 = __half2float(__low2half(oa));
                float a1 = __half2float(__high2half(oa));
                if (tig == 0) {
                    __stcs(&outSdf[pp], a0);
                    __stcs(&outRgb[(size_t)pp * 3 + 0], (tanhf(a1) + 1.0f) * 0.5f);
                } else {
                    __stcs(&outRgb[(size_t)pp * 3 + 1], (tanhf(a0) + 1.0f) * 0.5f);
                    __stcs(&outRgb[(size_t)pp * 3 + 2], (tanhf(a1) + 1.0f) * 0.5f);
                }
            }
        }
    }
    #undef W1S
    #undef W2S
}

extern "C" void kernel_launch(void* const* d_in, const int* in_sizes, int n_in,
                              void* d_out, int out_size)
{
    const float* x      = (const float*)d_in[0];
    const float* planes = (const float*)d_in[1];
    const float* W1     = (const float*)d_in[2];
    const float* b1     = (const float*)d_in[3];
    const float* W2     = (const float*)d_in[4];
    const float* b2     = (const float*)d_in[5];
    float* out = (float*)d_out;

    int N = in_sizes[0] / 3;

    const int threads = 256;
    const int ptsPerCta = (threads / 32) * 8;  // 64 points per CTA iteration
    int blocksFull = (N + ptsPerCta - 1) / ptsPerCta;
    int blocks = blocksFull < 4736 ? blocksFull : 4736;

    styleneus_fused<<<blocks, threads>>>(x, planes, W1, b1, W2, b2, out, N);
}

// round 8
// speedup vs baseline: 1.9644x; 1.0347x over previous
#include <cuda_runtime.h>
#include <cuda_fp16.h>

#define RESV 512
#define FULLM 0xffffffffu

typedef unsigned long long u64;

__device__ __forceinline__ void mma16816(float& d0, float& d1, float& d2, float& d3,
                                         unsigned a0, unsigned a1, unsigned a2, unsigned a3,
                                         unsigned b0, unsigned b1) {
    asm volatile("mma.sync.aligned.m16n8k16.row.col.f32.f16.f16.f32 "
                 "{%0,%1,%2,%3},{%4,%5,%6,%7},{%8,%9},{%0,%1,%2,%3};"
                 : "+f"(d0), "+f"(d1), "+f"(d2), "+f"(d3)
                 : "r"(a0), "r"(a1), "r"(a2), "r"(a3), "r"(b0), "r"(b1));
}

__device__ __forceinline__ unsigned packh2(__half lo, __half hi) {
    __half2 h = __halves2half2(lo, hi);
    return *reinterpret_cast<unsigned*>(&h);
}

__device__ __forceinline__ u64 mk_evict_last_policy() {
    u64 pol;
    asm("createpolicy.fractional.L2::evict_last.b64 %0, 1.0;" : "=l"(pol));
    return pol;
}

// ---- packed f32x2 helpers (Blackwell) ----
__device__ __forceinline__ u64 fma2(u64 a, u64 b, u64 c) {
    u64 d; asm("fma.rn.f32x2 %0, %1, %2, %3;" : "=l"(d) : "l"(a), "l"(b), "l"(c));
    return d;
}
__device__ __forceinline__ u64 add2(u64 a, u64 b) {
    u64 d; asm("add.rn.f32x2 %0, %1, %2;" : "=l"(d) : "l"(a), "l"(b));
    return d;
}
__device__ __forceinline__ u64 bcast2(float v) {
    u64 d; asm("mov.b64 %0, {%1, %1};" : "=l"(d) : "f"(v));
    return d;
}
__device__ __forceinline__ u64 pack2(float lo, float hi) {
    u64 d; asm("mov.b64 %0, {%1, %2};" : "=l"(d) : "f"(lo), "f"(hi));
    return d;
}
__device__ __forceinline__ void unpack2f(u64 v, float& lo, float& hi) {
    asm("mov.b64 {%0, %1}, %2;" : "=f"(lo), "=f"(hi) : "l"(v));
}

// 16-byte plane gather as two packed f32x2 words, evict-last hint
__device__ __forceinline__ ulonglong2 ldg_plane2(const float* p, u64 pol) {
    ulonglong2 v;
    asm volatile("ld.global.nc.L2::cache_hint.v2.u64 {%0,%1}, [%2], %3;"
                 : "=l"(v.x), "=l"(v.y) : "l"(p), "l"(pol));
    return v;
}

__global__ void __launch_bounds__(256, 3)
styleneus_fused(const float* __restrict__ x,
                const float* __restrict__ planes,
                const float* __restrict__ W1,
                const float* __restrict__ b1,
                const float* __restrict__ W2,
                const float* __restrict__ b2,
                float* __restrict__ out,
                int N)
{
    __shared__ unsigned wfrag[32 * 36];
    __shared__ __half stage[8 * 320];
    __shared__ __align__(16) float uback[256 * 12];

    const __half  sh     = __float2half(0.17677669529663689f);  // fp16(1/sqrt(32))
    const __half  hzero  = __float2half(0.0f);
    const __half2 zero2  = __float2half2_rn(0.0f);
    const __half2 slope2 = __float2half2_rn(0.2f);

    const u64 evlast = mk_evict_last_policy();
    const u64 neg1_2 = 0xBF800000BF800000ULL;  // {-1.0f, -1.0f}

    const int tid  = threadIdx.x;
    const int lane = tid & 31;
    const int f    = lane & 7;   // feature-slice (gather layout)
    const int g    = lane >> 3;  // point-in-pass (gather layout)
    const int tig  = lane & 3;   // mma thread-in-group
    const int gid  = lane >> 2;  // mma group id

    #define W1S(i, j) __hmul(__float2half(__ldg(&W1[(i) * 32 + (j)])), sh)
    #define W2S(i, j) __hmul(__float2half(__ldg(&W2[(i) * 4 + (j)])), sh)

    if (tid < 32) {
        unsigned* wl = wfrag + lane * 36;
        #pragma unroll
        for (int kt = 0; kt < 2; kt++)
            #pragma unroll
            for (int nt = 0; nt < 4; nt++) {
                int k0 = 16 * kt + 2 * tig;
                int jc = 8 * nt + gid;
                wl[kt * 8 + nt * 2 + 0] = packh2(W1S(k0,     jc), W1S(k0 + 1, jc));
                wl[kt * 8 + nt * 2 + 1] = packh2(W1S(k0 + 8, jc), W1S(k0 + 9, jc));
                wl[16 + kt * 8 + nt * 2 + 0] = packh2(W1S(jc, k0),     W1S(jc, k0 + 1));
                wl[16 + kt * 8 + nt * 2 + 1] = packh2(W1S(jc, k0 + 8), W1S(jc, k0 + 9));
            }
        #pragma unroll
        for (int kt = 0; kt < 2; kt++) {
            int k0 = 16 * kt + 2 * tig;
            if (gid < 4) {
                wl[32 + kt * 2 + 0] = packh2(W2S(k0,     gid), W2S(k0 + 1, gid));
                wl[32 + kt * 2 + 1] = packh2(W2S(k0 + 8, gid), W2S(k0 + 9, gid));
            } else {
                wl[32 + kt * 2 + 0] = 0;
                wl[32 + kt * 2 + 1] = 0;
            }
        }
    }
    __syncthreads();

    __half2 b1h2[4], wpos[4];
    #pragma unroll
    for (int nt = 0; nt < 4; nt++) {
        int c0 = 8 * nt + 2 * tig;
        b1h2[nt] = __halves2half2(__float2half(__ldg(&b1[c0])), __float2half(__ldg(&b1[c0 + 1])));
        wpos[nt] = __halves2half2(W2S(c0, 0), W2S(c0 + 1, 0));
    }
    __half2 b2p = zero2;
    if (tig < 2)
        b2p = __halves2half2(__float2half(__ldg(&b2[2 * tig])), __float2half(__ldg(&b2[2 * tig + 1])));

    float* __restrict__ outSdf = out;
    float* __restrict__ outH   = out + (size_t)N;
    float* __restrict__ outNab = out + (size_t)N * 33;
    float* __restrict__ outRgb = out + (size_t)N * 36;

    __half* st = stage + (tid >> 5) * 320;
    const uint4* wl4 = reinterpret_cast<const uint4*>(wfrag + lane * 36);
    ulonglong2*  ubq = reinterpret_cast<ulonglong2*>(uback + tid * 12);

    const int warpsPerCta = blockDim.x >> 5;
    int       warpId      = blockIdx.x * warpsPerCta + (tid >> 5);
    const int warpStride  = gridDim.x * warpsPerCta;

    for (; warpId * 8 < N; warpId += warpStride) {
        const int base = warpId * 8;

        // ---------- encode: 2 passes of 4 points, gather layout, f32x2 math ----------
        u64 U2[3][2];  // pass-local directional vectors (packed pairs)
        #pragma unroll
        for (int r = 0; r < 2; r++) {
            int  p     = base + 4 * r + g;
            bool valid = (p < N);
            int  pc    = valid ? p : (N - 1);

            float fr[3];
            int   i0[3], i1[3];
            #pragma unroll
            for (int d = 0; d < 3; d++) {
                float xv  = __ldcs(&x[pc * 3 + d]);
                float pos = (xv + 1.0f) * 0.5f * 511.0f;
                float fl  = floorf(pos);
                fr[d] = pos - fl;
                int q = (int)fl;
                q = q < 0 ? 0 : (q > 511 ? 511 : q);
                i0[d] = q;
                i1[d] = (q + 1 > 511) ? 511 : (q + 1);
            }

            u64 hq2[2] = {0ULL, 0ULL};
            #pragma unroll
            for (int d = 0; d < 3; d++) { U2[d][0] = 0ULL; U2[d][1] = 0ULL; }

            #pragma unroll
            for (int k = 0; k < 3; k++) {
                const int a = (k == 2) ? 1 : 0;
                const int b = (k == 0) ? 1 : 2;
                float fa = fr[a], fb = fr[b];
                const float* pb = planes + (size_t)k * (RESV * RESV * 32);
                int ra0 = i0[a] << 9, ra1 = i1[a] << 9;
                int cb0 = i0[b],      cb1 = i1[b];

                ulonglong2 c00 = ldg_plane2(pb + (((size_t)(ra0 + cb0)) << 5) + 4 * f, evlast);
                ulonglong2 c01 = ldg_plane2(pb + (((size_t)(ra0 + cb1)) << 5) + 4 * f, evlast);
                ulonglong2 c10 = ldg_plane2(pb + (((size_t)(ra1 + cb0)) << 5) + 4 * f, evlast);
                ulonglong2 c11 = ldg_plane2(pb + (((size_t)(ra1 + cb1)) << 5) + 4 * f, evlast);

                float ofa = 1.0f - fa, ofb = 1.0f - fb;
                u64 w00 = bcast2(ofa * ofb);
                u64 w01 = bcast2(ofa * fb);
                u64 w10 = bcast2(fa * ofb);
                u64 w11 = bcast2(fa * fb);
                u64 fa2 = bcast2(fa);
                u64 fb2 = bcast2(fb);

                const int da = (k == 2) ? 1 : 0;  // dim index of fa
                const int db = (k == 0) ? 1 : 2;  // dim index of fb
                #pragma unroll
                for (int hh = 0; hh < 2; hh++) {
                    u64 a00 = hh ? c00.y : c00.x;
                    u64 a01 = hh ? c01.y : c01.x;
                    u64 a10 = hh ? c10.y : c10.x;
                    u64 a11 = hh ? c11.y : c11.x;

                    hq2[hh] = fma2(w00, a00, hq2[hh]);
                    hq2[hh] = fma2(w01, a01, hq2[hh]);
                    hq2[hh] = fma2(w10, a10, hq2[hh]);
                    hq2[hh] = fma2(w11, a11, hq2[hh]);

                    // e1 = a10 - a00, e2 = a11 - a01  (d/dfa pieces)
                    u64 e1 = fma2(neg1_2, a00, a10);
                    u64 e2 = fma2(neg1_2, a01, a11);
                    u64 t1 = fma2(neg1_2, e1, e2);
                    u64 dua = fma2(fb2, t1, e1);
                    // e3 = a01 - a00, e4 = a11 - a10  (d/dfb pieces)
                    u64 e3 = fma2(neg1_2, a00, a01);
                    u64 e4 = fma2(neg1_2, a10, a11);
                    u64 t2 = fma2(neg1_2, e3, e4);
                    u64 dub = fma2(fa2, t2, e3);

                    U2[da][hh] = add2(U2[da][hh], dua);
                    U2[db][hh] = add2(U2[db][hh], dub);
                }
            }

            // unpack h for write + fp16 staging
            float h0f, h1f, h2f, h3f;
            unpack2f(hq2[0], h0f, h1f);
            unpack2f(hq2[1], h2f, h3f);

            if (valid) {
                float4 hv = make_float4(h0f, h1f, h2f, h3f);
                __stcs(reinterpret_cast<float4*>(outH + (size_t)p * 32 + 4 * f), hv);
            }

            unsigned hp0 = packh2(__float2half(h0f), __float2half(h1f));
            unsigned hp1 = packh2(__float2half(h2f), __float2half(h3f));
            *reinterpret_cast<uint2*>(st + (4 * r + g) * 40 + 4 * f) = make_uint2(hp0, hp1);

            if (r == 0) {
                // park pass-0 U pairs in smem
                ubq[0] = make_ulonglong2(U2[0][0], U2[0][1]);
                ubq[1] = make_ulonglong2(U2[1][0], U2[1][1]);
                ubq[2] = make_ulonglong2(U2[2][0], U2[2][1]);
            }
        }
        __syncwarp();

        // ---------- forward mma: Z[8,32] = H * W1s ----------
        unsigned aF[2][2];
        #pragma unroll
        for (int kt = 0; kt < 2; kt++) {
            aF[kt][0] = *reinterpret_cast<const unsigned*>(st + gid * 40 + 2 * tig + 16 * kt);
            aF[kt][1] = *reinterpret_cast<const unsigned*>(st + gid * 40 + 2 * tig + 16 * kt + 8);
        }
        unsigned wfb[16];
        *reinterpret_cast<uint4*>(wfb +  0) = wl4[0];
        *reinterpret_cast<uint4*>(wfb +  4) = wl4[1];
        *reinterpret_cast<uint4*>(wfb +  8) = wl4[2];
        *reinterpret_cast<uint4*>(wfb + 12) = wl4[3];
        float dF[4][4];
        #pragma unroll
        for (int nt = 0; nt < 4; nt++) {
            dF[nt][0] = dF[nt][1] = dF[nt][2] = dF[nt][3] = 0.0f;
            #pragma unroll
            for (int kt = 0; kt < 2; kt++)
                mma16816(dF[nt][0], dF[nt][1], dF[nt][2], dF[nt][3],
                         aF[kt][0], 0u, aF[kt][1], 0u,
                         wfb[kt * 8 + nt * 2], wfb[kt * 8 + nt * 2 + 1]);
        }

        // ---------- activation + cotangent (C layout) ----------
        unsigned y2[4], g2[4];
        #pragma unroll
        for (int nt = 0; nt < 4; nt++) {
            __half2 z2 = __floats2half2_rn(dF[nt][0], dF[nt][1]);
            __half2 yb = __hadd2(z2, b1h2[nt]);
            __half2 yl = __hfma2(__hmin2(yb, zero2), slope2, __hmax2(yb, zero2));
            y2[nt] = *reinterpret_cast<unsigned*>(&yl);
            __half2 wneg = __hmul2(slope2, wpos[nt]);
            __half glo = __hlt(__low2half(yb),  hzero) ? __low2half(wneg)  : __low2half(wpos[nt]);
            __half ghi = __hlt(__high2half(yb), hzero) ? __high2half(wneg) : __high2half(wpos[nt]);
            g2[nt] = packh2(glo, ghi);
        }

        // ---------- layer 2: O[8,4] = Y * W2s ----------
        float o0 = 0, o1 = 0, o2d = 0, o3d = 0;
        {
            uint4 w2f = wl4[8];
            mma16816(o0, o1, o2d, o3d, y2[0], 0u, y2[1], 0u, w2f.x, w2f.y);
            mma16816(o0, o1, o2d, o3d, y2[2], 0u, y2[3], 0u, w2f.z, w2f.w);
        }

        // ---------- backward: GH[8,32] = G * W1s^T ----------
        unsigned wbb[16];
        *reinterpret_cast<uint4*>(wbb +  0) = wl4[4];
        *reinterpret_cast<uint4*>(wbb +  4) = wl4[5];
        *reinterpret_cast<uint4*>(wbb +  8) = wl4[6];
        *reinterpret_cast<uint4*>(wbb + 12) = wl4[7];
        float dB[4][4];
        #pragma unroll
        for (int nt = 0; nt < 4; nt++) {
            dB[nt][0] = dB[nt][1] = dB[nt][2] = dB[nt][3] = 0.0f;
            #pragma unroll
            for (int kt = 0; kt < 2; kt++)
                mma16816(dB[nt][0], dB[nt][1], dB[nt][2], dB[nt][3],
                         g2[2 * kt], 0u, g2[2 * kt + 1], 0u,
                         wbb[kt * 8 + nt * 2], wbb[kt * 8 + nt * 2 + 1]);
        }
        __syncwarp();

        #pragma unroll
        for (int nt = 0; nt < 4; nt++) {
            unsigned pk = packh2(__float2half(dB[nt][0]), __float2half(dB[nt][1]));
            *reinterpret_cast<unsigned*>(st + gid * 40 + 8 * nt + 2 * tig) = pk;
        }
        __syncwarp();

        // ---------- nablas: gh . U per pass (f32x2), reduce over 8 lanes ----------
        float nb[2][3];
        #pragma unroll
        for (int r = 0; r < 2; r++) {
            uint2 gw = *reinterpret_cast<const uint2*>(st + (4 * r + g) * 40 + 4 * f);
            float2 g01f = __half22float2(*reinterpret_cast<__half2*>(&gw.x));
            float2 g23f = __half22float2(*reinterpret_cast<__half2*>(&gw.y));
            u64 g01 = pack2(g01f.x, g01f.y);
            u64 g23 = pack2(g23f.x, g23f.y);
            #pragma unroll
            for (int d = 0; d < 3; d++) {
                u64 u0, u1;
                if (r == 0) { ulonglong2 uq = ubq[d]; u0 = uq.x; u1 = uq.y; }
                else        { u0 = U2[d][0]; u1 = U2[d][1]; }
                u64 s2 = fma2(g01, u0, fma2(g23, u1, 0ULL));
                float slo, shi;
                unpack2f(s2, slo, shi);
                nb[r][d] = slo + shi;
            }
        }
        __syncwarp();

        // reduce-scatter over 8 lanes
        {
            float v0 = nb[0][0], v1 = nb[0][1], v2 = nb[0][2], v3 = 0.0f;
            float v4 = nb[1][0], v5 = nb[1][1], v6 = nb[1][2], v7 = 0.0f;
            bool hi4 = (f & 4) != 0;
            float t;
            t = __shfl_xor_sync(FULLM, hi4 ? v0 : v4, 4, 8); if (hi4) v4 += t; else v0 += t;
            t = __shfl_xor_sync(FULLM, hi4 ? v1 : v5, 4, 8); if (hi4) v5 += t; else v1 += t;
            t = __shfl_xor_sync(FULLM, hi4 ? v2 : v6, 4, 8); if (hi4) v6 += t; else v2 += t;
            float w0 = hi4 ? v4 : v0, w1 = hi4 ? v5 : v1, w2 = hi4 ? v6 : v2, w3 = hi4 ? v7 : v3;
            bool hi2 = (f & 2) != 0;
            t = __shfl_xor_sync(FULLM, hi2 ? w0 : w2, 2, 8); if (hi2) w2 += t; else w0 += t;
            t = __shfl_xor_sync(FULLM, hi2 ? w1 : w3, 2, 8); if (hi2) w3 += t; else w1 += t;
            float u0 = hi2 ? w2 : w0, u1 = hi2 ? w3 : w1;
            bool hi1 = (f & 1) != 0;
            t = __shfl_xor_sync(FULLM, hi1 ? u0 : u1, 1, 8); if (hi1) u1 += t; else u0 += t;
            float res = hi1 ? u1 : u0;

            int fm = f & 3;
            if (fm < 3) {
                int pp = base + ((f >> 2) << 2) + g;
                if (pp < N) __stcs(&outNab[(size_t)pp * 3 + fm], res * 511.0f);
            }
        }

        // ---------- sdf / rgb ----------
        if (tig < 2) {
            int pp = base + gid;
            if (pp < N) {
                __half2 oa = __hadd2(__floats2half2_rn(o0, o1), b2p);
                float a0 = __half2float(__low2half(oa));
                float a1 = __half2float(__high2half(oa));
                if (tig == 0) {
                    __stcs(&outSdf[pp], a0);
                    __stcs(&outRgb[(size_t)pp * 3 + 0], (tanhf(a1) + 1.0f) * 0.5f);
                } else {
                    __stcs(&outRgb[(size_t)pp * 3 + 1], (tanhf(a0) + 1.0f) * 0.5f);
                    __stcs(&outRgb[(size_t)pp * 3 + 2], (tanhf(a1) + 1.0f) * 0.5f);
                }
            }
        }
    }
    #undef W1S
    #undef W2S
}

extern "C" void kernel_launch(void* const* d_in, const int* in_sizes, int n_in,
                              void* d_out, int out_size)
{
    const float* x      = (const float*)d_in[0];
    const float* planes = (const float*)d_in[1];
    const float* W1     = (const float*)d_in[2];
    const float* b1     = (const float*)d_in[3];
    const float* W2     = (const float*)d_in[4];
    const float* b2     = (const float*)d_in[5];
    float* out = (float*)d_out;

    int N = in_sizes[0] / 3;

    const int threads = 256;
    const int ptsPerCta = (threads / 32) * 8;  // 64 points per CTA iteration
    int blocksFull = (N + ptsPerCta - 1) / ptsPerCta;
    int blocks = blocksFull < 4736 ? blocksFull : 4736;

    styleneus_fused<<<blocks, threads>>>(x, planes, W1, b1, W2, b2, out, N);
}